// round 13
// baseline (speedup 1.0000x reference)
#include <cuda_runtime.h>
#include <stdint.h>
#include <math.h>

// Problem constants (fixed by the dataset)
#define H   128
#define OO  20
#define KI  700
#define BB  256
#define TT  250
#define MTOT (BB * TT)   // 64000

// Scratch for the hoisted input projection: xin[(b*T + t)][h]
__device__ float g_xin[(size_t)MTOT * H];

// ---------------------------------------------------------------------------
// f32x2 packed helpers (sm_103a). fma.rn.f32x2 = two independent rn fp32 FMAs
// in one fma-pipe instruction -> bitwise identical to two fmaf.
// ---------------------------------------------------------------------------
typedef unsigned long long ull;

__device__ __forceinline__ ull pk2(float lo, float hi) {
    ull r;
    asm("mov.b64 %0, {%1, %2};" : "=l"(r) : "f"(lo), "f"(hi));
    return r;
}
__device__ __forceinline__ void upk2(float& lo, float& hi, ull v) {
    asm("mov.b64 {%0, %1}, %2;" : "=f"(lo), "=f"(hi) : "l"(v));
}
__device__ __forceinline__ void ffma2(ull& acc, ull a, ull b) {
    asm("fma.rn.f32x2 %0, %1, %2, %0;" : "+l"(acc) : "l"(a), "l"(b));
}

// cp.async wrappers
__device__ __forceinline__ void cpa4(unsigned int dst, const void* src) {
    asm volatile("cp.async.ca.shared.global [%0], [%1], 4;" :: "r"(dst), "l"(src));
}
__device__ __forceinline__ void cpa16(unsigned int dst, const void* src) {
    asm volatile("cp.async.cg.shared.global [%0], [%1], 16;" :: "r"(dst), "l"(src));
}
__device__ __forceinline__ void cpa_commit() {
    asm volatile("cp.async.commit_group;");
}
__device__ __forceinline__ void cpa_wait_1() {
    asm volatile("cp.async.wait_group 1;");
}

// ---------------------------------------------------------------------------
// Bit-exact transcription of XLA CPU's vectorized expf (Cephes/Eigen pexp).
// ---------------------------------------------------------------------------
__device__ __forceinline__ float xla_expf(float xin_) {
    const float exp_hi = 88.3762626647950f;
    const float exp_lo = -88.3762626647949f;
    const float LOG2EF = 1.44269504088896341f;
    const float C1 = 0.693359375f;
    const float C2 = -2.12194440e-4f;
    const float p0 = 1.9875691500E-4f;
    const float p1 = 1.3981999507E-3f;
    const float p2 = 8.3334519073E-3f;
    const float p3 = 4.1665795894E-2f;
    const float p4 = 1.6666665459E-1f;
    const float p5 = 5.0000001201E-1f;

    float x = fminf(fmaxf(xin_, exp_lo), exp_hi);
    float fx = floorf(__fadd_rn(__fmul_rn(x, LOG2EF), 0.5f));
    float tmp = __fmul_rn(C1, fx);
    float z   = __fmul_rn(C2, fx);
    float xx  = __fsub_rn(x, tmp);
    xx = __fsub_rn(xx, z);
    z = __fmul_rn(xx, xx);
    float y = __fadd_rn(__fmul_rn(xx, p0), p1);
    y = __fadd_rn(__fmul_rn(y, xx), p2);
    y = __fadd_rn(__fmul_rn(y, xx), p3);
    y = __fadd_rn(__fmul_rn(y, xx), p4);
    y = __fadd_rn(__fmul_rn(y, xx), p5);
    y = __fadd_rn(__fmul_rn(y, z), xx);
    y = __fadd_rn(1.0f, y);
    int n = (int)fx;
    float p2n = __int_as_float((n + 127) << 23);
    float r = __fmul_rn(y, p2n);
    return fmaxf(r, xin_);
}

// ---------------------------------------------------------------------------
// Phase 1: xin = x @ w_ih1 + b_ih1  (unchanged from R12: 3-stage cp.async)
// ---------------------------------------------------------------------------
#define BM  128
#define BN  128
#define BKK 16
#define NT  44
#define ASTRIDE (BM + 4)
#define STG 3

__global__ __launch_bounds__(256, 2)
void gemm_xin_kernel(const float* __restrict__ x,
                     const float* __restrict__ w,
                     const float* __restrict__ bias)
{
    __shared__ float As[STG][BKK][ASTRIDE];
    __shared__ float Bs[STG][BKK][BN];

    const int tid     = threadIdx.x;
    const int block_m = blockIdx.x * BM;
    const int tn      = tid & 15;
    const int tm      = tid >> 4;

    const int ka = tid & 15, ra = tid >> 4;
    const int brow = tid >> 5, bcol4 = tid & 31;

    ull acc2[8][4];
#pragma unroll
    for (int i = 0; i < 8; i++)
#pragma unroll
        for (int j = 0; j < 4; j++) acc2[i][j] = 0ull;

    auto issue_loads = [&](int it, int buf) {
        int k0 = it * BKK;
#pragma unroll
        for (int p = 0; p < 8; p++) {
            int kk = k0 + ka;
            int m  = ra + p * 16;
            int row = block_m + m;
            if (kk < KI) {
                unsigned int dst =
                    (unsigned int)__cvta_generic_to_shared(&As[buf][ka][m]);
                cpa4(dst, x + (size_t)row * KI + kk);
            } else {
                As[buf][ka][m] = 0.f;
            }
        }
#pragma unroll
        for (int q = 0; q < 2; q++) {
            int r = brow + q * 8;
            int kk = k0 + r;
            if (kk < KI) {
                unsigned int dst =
                    (unsigned int)__cvta_generic_to_shared(&Bs[buf][r][bcol4 * 4]);
                cpa16(dst, w + (size_t)kk * H + bcol4 * 4);
            } else {
                *(float4*)&Bs[buf][r][bcol4 * 4] = make_float4(0.f, 0.f, 0.f, 0.f);
            }
        }
        cpa_commit();
    };

    issue_loads(0, 0);
    issue_loads(1, 1);

    for (int it = 0; it < NT; it++) {
        cpa_wait_1();
        __syncthreads();
        if (it + 2 < NT) issue_loads(it + 2, (it + 2) % STG);
        else             cpa_commit();
        const int cur = it % STG;

#pragma unroll
        for (int k = 0; k < BKK; k++) {
            const float4* ap = (const float4*)&As[cur][k][tm * 8];
            const float4* bp = (const float4*)&Bs[cur][k][tn * 8];
            float4 a0 = ap[0], a1 = ap[1];
            float4 b0 = bp[0], b1 = bp[1];
            ull bp0 = pk2(b0.x, b0.y);
            ull bp1 = pk2(b0.z, b0.w);
            ull bp2 = pk2(b1.x, b1.y);
            ull bp3 = pk2(b1.z, b1.w);
            float av[8];
            av[0]=a0.x; av[1]=a0.y; av[2]=a0.z; av[3]=a0.w;
            av[4]=a1.x; av[5]=a1.y; av[6]=a1.z; av[7]=a1.w;
#pragma unroll
            for (int i = 0; i < 8; i++) {
                ull apk = pk2(av[i], av[i]);
                ffma2(acc2[i][0], apk, bp0);
                ffma2(acc2[i][1], apk, bp1);
                ffma2(acc2[i][2], apk, bp2);
                ffma2(acc2[i][3], apk, bp3);
            }
        }
    }

#pragma unroll
    for (int i = 0; i < 8; i++) {
        int row = block_m + tm * 8 + i;
#pragma unroll
        for (int jp = 0; jp < 4; jp++) {
            float lo, hi;
            upk2(lo, hi, acc2[i][jp]);
            int col = tn * 8 + 2 * jp;
            g_xin[(size_t)row * H + col]     = __fadd_rn(lo, bias[col]);
            g_xin[(size_t)row * H + col + 1] = __fadd_rn(hi, bias[col + 1]);
        }
    }
}

// ---------------------------------------------------------------------------
// Phase 2: scan, warp-specialized. 384 threads / block, 2 batches / block.
//   G0 (tid   0-127): per-neuron state + elementwise + d1 chain (w11 smem)
//   G1 (tid 128-255): d12 chain, w12 column in REGISTERS
//   G2 (tid 256-383): d22 chain, w22*mask column in REGISTERS
// Batch-packed ffma2: each lane keeps the exact scalar ascending chain.
// 2 barriers / step. SMEM (float offsets):
//   W11S [0,16384)       w11*mask  [h][g]
//   WOS  [16384,18944)   w_h2o
//   SP1  [18944,19200)   float2 {s1A,s1B}[128]
//   SP2  [19200,19456)   float2 {s2A,s2B}[128]
//   DB12 [19456,19712)   float2 {d12A,d12B}[128]
//   DB22 [19712,19968)   float2 {d22A,d22B}[128]
//   MKH  [19968,21968)   [2][250][4] u32 layer-2 ballots
//   OBUF [21968,31968)   [2][250][20] io -> om -> softmax
// Total 31968 floats = 127872 bytes.
// ---------------------------------------------------------------------------
#define W11SO 0
#define WOSO  16384
#define SP1O  18944
#define SP2O  19200
#define DB12O 19456
#define DB22O 19712
#define MKHO  19968
#define OBUFO 21968
#define SCAN_SMEM_BYTES (31968 * 4)

__global__ __launch_bounds__(384, 1)
void snn_scan_kernel(const float* __restrict__ mask,
                     const float* __restrict__ w11g, const float* __restrict__ b11g,
                     const float* __restrict__ w12g, const float* __restrict__ b12g,
                     const float* __restrict__ w22g, const float* __restrict__ b22g,
                     const float* __restrict__ wog,  const float* __restrict__ bog,
                     const float* __restrict__ tau_adp1, const float* __restrict__ tau_adp2,
                     const float* __restrict__ tau_m1,   const float* __restrict__ tau_m2,
                     const float* __restrict__ tau_mo,
                     const float* __restrict__ h1m0, const float* __restrict__ h2m0,
                     const float* __restrict__ om0,
                     float* __restrict__ out_acc,
                     float* __restrict__ out_s1,
                     float* __restrict__ out_s2)
{
    extern __shared__ float smf[];
    float*      w11s = smf + W11SO;
    float*      wos  = smf + WOSO;
    float2*     sp1  = (float2*)(smf + SP1O);
    float2*     sp2  = (float2*)(smf + SP2O);
    float2*     db12 = (float2*)(smf + DB12O);
    float2*     db22 = (float2*)(smf + DB22O);
    unsigned*   mkh  = (unsigned*)(smf + MKHO);
    float*      obuf = smf + OBUFO;

    const int tid  = threadIdx.x;
    const int grp  = tid >> 7;          // 0,1,2
    const int g    = tid & (H - 1);     // neuron / column index within group
    const int lane = tid & 31;
    const int wig  = g >> 5;
    const int b0   = blockIdx.x * 2;

    // ---- staging: w11*mask + wos into smem; zero spike buffers ----
    for (int i = tid; i < H * H; i += 384)
        w11s[i] = __fmul_rn(w11g[i], mask[i]);
    for (int i = tid; i < H * OO; i += 384) wos[i] = wog[i];
    if (tid < 128) {
        sp1[tid] = make_float2(0.f, 0.f);
        sp2[tid] = make_float2(0.f, 0.f);
    }

    // ---- G1/G2: weight column in registers (fully unrolled indexing) ----
    float wreg[H];
    if (grp == 1) {
#pragma unroll
        for (int hp = 0; hp < H; hp++)
            wreg[hp] = w12g[hp * H + g];
    } else if (grp == 2) {
#pragma unroll
        for (int hp = 0; hp < H; hp++)
            wreg[hp] = __fmul_rn(w22g[hp * H + g], mask[H * H + hp * H + g]);
    }

    // ---- G0: per-neuron constants & state (both batches) ----
    float a1 = 0, r1 = 0, a2 = 0, r2 = 0, om_a1 = 0, om_r1 = 0, om_a2 = 0, om_r2 = 0;
    float bi1 = 0, b12c = 0, b22c = 0;
    float h1m[2], h2m[2], bb1[2], bb2[2], spk1[2], spk2[2], s1c[2], s2c[2];
    float xcur[2], xnxt[2];
    const float* xrow[2] = {0, 0};
    ull d1p = 0ull;

    if (grp == 0) {
        a1 = xla_expf(__fdiv_rn(-1.f, tau_m1[g]));
        r1 = xla_expf(__fdiv_rn(-1.f, tau_adp1[g]));
        a2 = xla_expf(__fdiv_rn(-1.f, tau_m2[g]));
        r2 = xla_expf(__fdiv_rn(-1.f, tau_adp2[g]));
        om_a1 = __fsub_rn(1.f, a1);
        om_r1 = __fsub_rn(1.f, r1);
        om_a2 = __fsub_rn(1.f, a2);
        om_r2 = __fsub_rn(1.f, r2);
        bi1 = b11g[g]; b12c = b12g[g]; b22c = b22g[g];
#pragma unroll
        for (int nb = 0; nb < 2; nb++) {
            int b = b0 + nb;
            h1m[nb] = h1m0[b * H + g];
            h2m[nb] = h2m0[b * H + g];
            bb1[nb] = 0.01f; bb2[nb] = 0.01f;
            spk1[nb] = 0.f;  spk2[nb] = 0.f;
            s1c[nb] = 0.f;   s2c[nb] = 0.f;
            xrow[nb] = g_xin + (size_t)b * TT * H + g;
            xcur[nb] = xrow[nb][0];
        }
    }
    __syncthreads();

    // L2 elementwise for step t (G0 only); reads db12/db22, updates state,
    // publishes sp2 pairs + ballots for mkh[t].
    auto l2elem = [&](int t) {
        float2 v12 = db12[g];
        float2 v22 = db22[g];
        float ns2v[2];
#pragma unroll
        for (int nb = 0; nb < 2; nb++) {
            float d12 = nb ? v12.y : v12.x;
            float d22 = nb ? v22.y : v22.x;
            float i2 = __fadd_rn(__fadd_rn(__fadd_rn(d12, b12c), d22), b22c);
            bb2[nb] = __fadd_rn(__fmul_rn(r2, bb2[nb]), __fmul_rn(om_r2, spk2[nb]));
            float B2 = __fadd_rn(0.01f, __fmul_rn(1.8f, bb2[nb]));
            h2m[nb] = __fsub_rn(__fadd_rn(__fmul_rn(h2m[nb], a2), __fmul_rn(om_a2, i2)),
                                __fmul_rn(B2, spk2[nb]));
            float ns2 = (__fsub_rn(h2m[nb], B2) > 0.f) ? 1.f : 0.f;
            s2c[nb] = __fadd_rn(s2c[nb], ns2);
            spk2[nb] = ns2;
            ns2v[nb] = ns2;
        }
        unsigned balA = __ballot_sync(0xffffffffu, ns2v[0] != 0.f);
        unsigned balB = __ballot_sync(0xffffffffu, ns2v[1] != 0.f);
        if (lane == 0) {
            mkh[(0 * TT + t) * 4 + wig] = balA;
            mkh[(1 * TT + t) * 4 + wig] = balB;
        }
        sp2[g] = make_float2(ns2v[0], ns2v[1]);
    };

#pragma unroll 1
    for (int k = 0; k < TT; k++) {
        // ================= phase (a): G0 elementwise =================
        if (grp == 0) {
            if (k > 0) l2elem(k - 1);
            // L1 elementwise for step k (uses d1p = d1(k))
            float d1A, d1B;
            upk2(d1A, d1B, d1p);
            float ns1v[2];
#pragma unroll
            for (int nb = 0; nb < 2; nb++) {
                float d1 = nb ? d1B : d1A;
                float i1 = __fadd_rn(__fadd_rn(xcur[nb], d1), bi1);
                bb1[nb] = __fadd_rn(__fmul_rn(r1, bb1[nb]), __fmul_rn(om_r1, spk1[nb]));
                float B1 = __fadd_rn(0.01f, __fmul_rn(1.8f, bb1[nb]));
                h1m[nb] = __fsub_rn(__fadd_rn(__fmul_rn(h1m[nb], a1), __fmul_rn(om_a1, i1)),
                                    __fmul_rn(B1, spk1[nb]));
                float ns1 = (__fsub_rn(h1m[nb], B1) > 0.f) ? 1.f : 0.f;
                s1c[nb] = __fadd_rn(s1c[nb], ns1);
                spk1[nb] = ns1;
                ns1v[nb] = ns1;
                xnxt[nb] = (k + 1 < TT) ? xrow[nb][(size_t)(k + 1) * H] : 0.f;
            }
            sp1[g] = make_float2(ns1v[0], ns1v[1]);
        }
        __syncthreads();

        // ================= phase (b): three chain groups =================
        if (grp == 0) {
            // d1(k+1) from sp1 (= s1(k)) with smem w11
            ull acc = 0ull;
            const ulonglong2* sq = (const ulonglong2*)sp1;
#pragma unroll
            for (int c = 0; c < 64; c++) {
                ulonglong2 q = sq[c];
                float wa = w11s[(2 * c) * H + g];
                float wb = w11s[(2 * c + 1) * H + g];
                ffma2(acc, q.x, pk2(wa, wa));
                ffma2(acc, q.y, pk2(wb, wb));
            }
            d1p = acc;
            xcur[0] = xnxt[0]; xcur[1] = xnxt[1];
        } else if (grp == 1) {
            // d12(k) from sp1 with register w12
            ull acc = 0ull;
            const ulonglong2* sq = (const ulonglong2*)sp1;
#pragma unroll
            for (int c = 0; c < 64; c++) {
                ulonglong2 q = sq[c];
                ffma2(acc, q.x, pk2(wreg[2 * c], wreg[2 * c]));
                ffma2(acc, q.y, pk2(wreg[2 * c + 1], wreg[2 * c + 1]));
            }
            float lo, hi; upk2(lo, hi, acc);
            db12[g] = make_float2(lo, hi);
        } else {
            // d22(k) from sp2 (= s2(k-1)) with register w22m
            ull acc = 0ull;
            const ulonglong2* sq = (const ulonglong2*)sp2;
#pragma unroll
            for (int c = 0; c < 64; c++) {
                ulonglong2 q = sq[c];
                ffma2(acc, q.x, pk2(wreg[2 * c], wreg[2 * c]));
                ffma2(acc, q.y, pk2(wreg[2 * c + 1], wreg[2 * c + 1]));
            }
            float lo, hi; upk2(lo, hi, acc);
            db22[g] = make_float2(lo, hi);
        }
        __syncthreads();
    }

    // epilogue: final layer-2 elementwise for t = TT-1
    if (grp == 0) l2elem(TT - 1);
    __syncthreads();

    // ---- P1: io(nb,t,o) = asc-chain(s2(t) * w_h2o[:,o]) + b_h2o[o] ----
    for (int idx = tid; idx < 2 * TT * OO; idx += 384) {
        int nb = idx / (TT * OO);
        int rem = idx - nb * (TT * OO);
        int t = rem / OO;
        int o = rem - t * OO;
        const unsigned* mh = mkh + (nb * TT + t) * 4;
        float io = 0.f;
#pragma unroll
        for (int w4 = 0; w4 < 4; w4++) {
            unsigned m = mh[w4];
            const float* wb = wos + (w4 * 32) * OO + o;
#pragma unroll
            for (int hb = 0; hb < 32; hb++) {
                if (m & 1u) io = __fadd_rn(io, wb[hb * OO]);
                m >>= 1;
            }
        }
        io = __fadd_rn(io, bog[o]);
        obuf[idx] = io;
    }
    __syncthreads();

    // ---- P2: om recurrence (serial in t; parallel over 2x20 channels) ----
    if (tid < 2 * OO) {
        int nb = tid / OO;
        int o  = tid - nb * OO;
        float omv    = om0[(b0 + nb) * OO + o];
        float aov    = xla_expf(__fdiv_rn(-1.f, tau_mo[o]));
        float om_aov = __fsub_rn(1.f, aov);
        float* ob = obuf + nb * (TT * OO) + o;
#pragma unroll 1
        for (int t = 0; t < TT; t++) {
            omv = __fadd_rn(__fmul_rn(omv, aov), __fmul_rn(om_aov, ob[t * OO]));
            ob[t * OO] = omv;
        }
    }
    __syncthreads();

    // ---- P3: softmax per (nb,t), in place ----
    for (int idx = tid; idx < 2 * TT; idx += 384) {
        int nb = idx / TT;
        int t  = idx - nb * TT;
        if (t > 10) {
            float* r = obuf + (nb * TT + t) * OO;
            float mx = r[0];
#pragma unroll
            for (int j = 1; j < OO; j++) mx = fmaxf(mx, r[j]);
            float ev[OO];
            float ssum = 0.f;
#pragma unroll
            for (int j = 0; j < OO; j++) {
                ev[j] = xla_expf(__fsub_rn(r[j], mx));
                ssum = __fadd_rn(ssum, ev[j]);
            }
#pragma unroll
            for (int j = 0; j < OO; j++) r[j] = __fdiv_rn(ev[j], ssum);
        }
    }
    __syncthreads();

    // ---- P4: acc = ascending-t sum of softmax (t>10) ----
    if (tid < 2 * OO) {
        int nb = tid / OO;
        int o  = tid - nb * OO;
        const float* ob = obuf + nb * (TT * OO) + o;
        float acc = 0.f;
#pragma unroll 1
        for (int t = 11; t < TT; t++)
            acc = __fadd_rn(acc, ob[t * OO]);
        out_acc[(b0 + nb) * OO + o] = acc;
    }

    if (grp == 0) {
#pragma unroll
        for (int nb = 0; nb < 2; nb++) {
            out_s1[(b0 + nb) * H + g] = __fdiv_rn(s1c[nb], 250.f);
            out_s2[(b0 + nb) * H + g] = __fdiv_rn(s2c[nb], 250.f);
        }
    }
}

// ---------------------------------------------------------------------------
// A_norm = sum |w_h1h1 * mask0| + sum |w_h2h2 * mask1|
// ---------------------------------------------------------------------------
__global__ void anorm_kernel(const float* __restrict__ w11g,
                             const float* __restrict__ w22g,
                             const float* __restrict__ mask,
                             float* __restrict__ out)
{
    __shared__ float red[256];
    float s1 = 0.f, s2 = 0.f;
    for (int i = threadIdx.x; i < H * H; i += 256) {
        s1 = __fadd_rn(s1, fabsf(__fmul_rn(w11g[i], mask[i])));
        s2 = __fadd_rn(s2, fabsf(__fmul_rn(w22g[i], mask[H * H + i])));
    }
    red[threadIdx.x] = __fadd_rn(s1, s2);
    __syncthreads();
    for (int st = 128; st; st >>= 1) {
        if (threadIdx.x < st)
            red[threadIdx.x] = __fadd_rn(red[threadIdx.x], red[threadIdx.x + st]);
        __syncthreads();
    }
    if (threadIdx.x == 0) out[0] = red[0];
}

// ---------------------------------------------------------------------------
extern "C" void kernel_launch(void* const* d_in, const int* in_sizes, int n_in,
                              void* d_out, int out_size)
{
    const float* x          = (const float*)d_in[0];
    const float* mask       = (const float*)d_in[1];
    const float* w_ih1      = (const float*)d_in[2];
    const float* b_ih1      = (const float*)d_in[3];
    const float* w_h1h1     = (const float*)d_in[4];
    const float* b_h1h1     = (const float*)d_in[5];
    const float* w_h1h2     = (const float*)d_in[6];
    const float* b_h1h2     = (const float*)d_in[7];
    const float* w_h2h2     = (const float*)d_in[8];
    const float* b_h2h2     = (const float*)d_in[9];
    const float* w_h2o      = (const float*)d_in[10];
    const float* b_h2o      = (const float*)d_in[11];
    const float* tau_adp_h1 = (const float*)d_in[12];
    const float* tau_adp_h2 = (const float*)d_in[13];
    const float* tau_m_h1   = (const float*)d_in[14];
    const float* tau_m_h2   = (const float*)d_in[15];
    const float* tau_m_o    = (const float*)d_in[16];
    const float* h1m0       = (const float*)d_in[17];
    const float* h2m0       = (const float*)d_in[18];
    const float* om0        = (const float*)d_in[19];

    float* out = (float*)d_out;
    float* out_acc = out;
    float* out_s1  = out + BB * OO;
    float* out_s2  = out + BB * OO + BB * H;
    float* out_an  = out + BB * OO + 2 * BB * H;

    cudaFuncSetAttribute(snn_scan_kernel,
                         cudaFuncAttributeMaxDynamicSharedMemorySize,
                         SCAN_SMEM_BYTES);

    gemm_xin_kernel<<<MTOT / BM, 256>>>(x, w_ih1, b_ih1);

    snn_scan_kernel<<<BB / 2, 384, SCAN_SMEM_BYTES>>>(
        mask,
        w_h1h1, b_h1h1, w_h1h2, b_h1h2, w_h2h2, b_h2h2, w_h2o, b_h2o,
        tau_adp_h1, tau_adp_h2, tau_m_h1, tau_m_h2, tau_m_o,
        h1m0, h2m0, om0,
        out_acc, out_s1, out_s2);

    anorm_kernel<<<1, 256>>>(w_h1h1, w_h2h2, mask, out_an);
}